// round 16
// baseline (speedup 1.0000x reference)
#include <cuda_runtime.h>
#include <cuda_bf16.h>
#include <cstdint>

// ---------------------------------------------------------------------------
// MultiHeadSelfAttention, b=2, s=2048, DIM=HIDDEN=1024, 16 heads, fp32.
// SCALE = 1024^-5 = 2^-50  =>  |scores| < ~3e-14. In fp32, exp(s - max)
// rounds to exactly 1.0f for every unmasked entry (and 0 for masked), so the
// reference softmax is EXACTLY uniform over unmasked positions:
//   attn[h,b,i,j] = mask[b,j] / n[b],   n[b] = sum_j mask[b,j]
//   out[b,i,:]    = ((sum_j mask[b,j]*x[b,j,:]) / n[b]) @ Wv^T @ Wo^T
// independent of i. Critical path = prep (fast) + mandatory 512 MB attn
// write at the HBM store floor; the out-chain hides on a side stream.
//
// Fill-shape sweep (rows/block @ 512 thr): 32 -> 119.6, 16 -> 88.4-88.9 (x5).
// This round probes the last untested neighbor: 8 rows/block (grid 8192,
// 64 KB contiguous/block) — 2x block supply, same store pattern.
// ---------------------------------------------------------------------------

#define SEQ   2048
#define DIMSZ 1024
#define NH    16
#define MROWS 4096   // b*s
#define NB    2
#define NCHUNK 32    // xbar stage-1 chunks per batch
#define FILL_RPB 8                              // rows per fill block
#define FILL_GRID (NH * NB * (SEQ / FILL_RPB))  // 8192

__device__ __align__(16) float g_rowpat[NB * SEQ];          // mask ? 1/n : 0
__device__ __align__(16) float g_inv[NB];                   // 1 / n[b]
__device__ __align__(16) float g_part[NB * NCHUNK * DIMSZ]; // stage-1 partials
__device__ __align__(16) float g_xbar[NB * DIMSZ];
__device__ __align__(16) float g_vbar[NB * DIMSZ];
__device__ __align__(16) float g_obar[NB * DIMSZ];

// Side stream + events for fork/join overlap inside graph capture.
// Created once at load time (host-side API; no device memory allocation).
struct StreamHolder {
  cudaStream_t s = nullptr;
  cudaEvent_t e_fork = nullptr, e_join = nullptr;
  bool ok = false;
  StreamHolder() {
    ok = (cudaStreamCreateWithFlags(&s, cudaStreamNonBlocking) == cudaSuccess) &&
         (cudaEventCreateWithFlags(&e_fork, cudaEventDisableTiming) == cudaSuccess) &&
         (cudaEventCreateWithFlags(&e_join, cudaEventDisableTiming) == cudaSuccess);
  }
};
static StreamHolder g_sh;

// ---------------------------------------------------------------------------
// 1) prep: mask row -> count -> inv[b] + rowpat (mask ? inv : 0).
//    grid(NB), block(512). One int4 mask load / one float4 rowpat store per
//    thread; warp shuffle reduce + single smem combine (2 barriers total).
// ---------------------------------------------------------------------------
__global__ __launch_bounds__(512) void prep_kernel(const int* __restrict__ mask) {
  __shared__ int red[16];
  __shared__ float s_inv;
  const int b = blockIdx.x;
  const int tid = threadIdx.x;
  int4 mk = __ldg((const int4*)(mask + b * SEQ) + tid);
  int s = (mk.x != 0) + (mk.y != 0) + (mk.z != 0) + (mk.w != 0);
#pragma unroll
  for (int d = 16; d >= 1; d >>= 1) s += __shfl_xor_sync(0xffffffffu, s, d);
  if ((tid & 31) == 0) red[tid >> 5] = s;
  __syncthreads();
  if (tid == 0) {
    int t = 0;
#pragma unroll
    for (int w = 0; w < 16; w++) t += red[w];
    float inv = 1.0f / (float)t;
    s_inv = inv;
    g_inv[b] = inv;
  }
  __syncthreads();
  const float inv = s_inv;
  float4 v;
  v.x = mk.x ? inv : 0.f;
  v.y = mk.y ? inv : 0.f;
  v.z = mk.z ? inv : 0.f;
  v.w = mk.w ? inv : 0.f;
  ((float4*)(g_rowpat + b * SEQ))[tid] = v;
}

// ---------------------------------------------------------------------------
// 2a) Stage-1 masked column sums: 64 j-rows per block.
//     grid(DIMSZ/256, NCHUNK, NB), block(256)
// ---------------------------------------------------------------------------
__global__ __launch_bounds__(256) void xbar1_kernel(const float* __restrict__ x,
                                                    const int* __restrict__ mask) {
  const int d = blockIdx.x * 256 + threadIdx.x;
  const int chunk = blockIdx.y;
  const int b = blockIdx.z;
  const int j0 = chunk * (SEQ / NCHUNK);      // 64 rows
  float s = 0.f;
  const float* xp = x + ((size_t)b * SEQ + j0) * DIMSZ + d;
  const int* mp = mask + b * SEQ + j0;
#pragma unroll 8
  for (int j = 0; j < SEQ / NCHUNK; j++)
    if (mp[j] != 0) s += xp[(size_t)j * DIMSZ];
  g_part[((b * NCHUNK) + chunk) * DIMSZ + d] = s;
}

// 2b) Stage-2: sum NCHUNK partials, scale by inv[b].
//     grid(DIMSZ/256, NB), block(256)
__global__ void xbar2_kernel() {
  const int d = blockIdx.x * 256 + threadIdx.x;
  const int b = blockIdx.y;
  float s = 0.f;
#pragma unroll
  for (int c = 0; c < NCHUNK; c++) s += g_part[((b * NCHUNK) + c) * DIMSZ + d];
  g_xbar[b * DIMSZ + d] = s * g_inv[b];
}

// ---------------------------------------------------------------------------
// 3) GEMV: outv[b][o] = sum_d in[b][d] * W[o][d].
//    Block 256 = 8 warps; 4 outputs/block, 2 warps/output (K split in half).
//    grid(DIMSZ/4, NB)
// ---------------------------------------------------------------------------
__global__ __launch_bounds__(256) void gemv_kernel(
    const float* __restrict__ W, const float* __restrict__ in,
    float* __restrict__ outv) {
  __shared__ float part[8];
  const int b = blockIdx.y;
  const int warp = threadIdx.x >> 5;
  const int lane = threadIdx.x & 31;
  const int o = blockIdx.x * 4 + (warp >> 1);
  const int half = warp & 1;
  const float4* wp = (const float4*)(W + (size_t)o * DIMSZ) + half * 128;
  const float4* vp = (const float4*)(in + b * DIMSZ) + half * 128;
  float acc = 0.f;
#pragma unroll
  for (int it = 0; it < 4; it++) {
    float4 w = wp[it * 32 + lane];
    float4 v = __ldg(&vp[it * 32 + lane]);
    acc = fmaf(w.x, v.x, acc);
    acc = fmaf(w.y, v.y, acc);
    acc = fmaf(w.z, v.z, acc);
    acc = fmaf(w.w, v.w, acc);
  }
#pragma unroll
  for (int d = 16; d >= 1; d >>= 1) acc += __shfl_xor_sync(0xffffffffu, acc, d);
  if (lane == 0) part[warp] = acc;
  __syncthreads();
  if (threadIdx.x < 4)
    outv[b * DIMSZ + blockIdx.x * 4 + threadIdx.x] =
        part[2 * threadIdx.x] + part[2 * threadIdx.x + 1];
}

// ---------------------------------------------------------------------------
// 4) Broadcast obar to all sequence rows.  grid(MROWS/8), block(512):
//    512 threads = 2 row-halves x 256 float4; each block writes 8 rows.
// ---------------------------------------------------------------------------
__global__ __launch_bounds__(512) void bcast_out_kernel(float* __restrict__ out) {
  const int r0 = blockIdx.x * 8;
  const int b = r0 >> 11;                       // 8 rows never straddle b
  const int f4 = threadIdx.x & 255;
  const int rh = threadIdx.x >> 8;              // 0 or 1: row parity
  float4 v = __ldg((const float4*)(g_obar + b * DIMSZ) + f4);
  float4* dst = (float4*)(out + (size_t)r0 * DIMSZ) + rh * (DIMSZ / 4) + f4;
#pragma unroll
  for (int r = 0; r < 4; r++)
    __stcs(dst + r * 2 * (DIMSZ / 4), v);
}

// ---------------------------------------------------------------------------
// 5) attn fill: one block = fixed (h,b), FILL_RPB=8 consecutive i rows
//    (64 KB contiguous); value = one float4 of g_rowpat per thread, held in
//    a register; 8 streaming row stores. grid(8192), block(512).
// ---------------------------------------------------------------------------
__global__ __launch_bounds__(512) void attn_fill_kernel(float* __restrict__ attn) {
  const int blk = blockIdx.x;
  const int chunks = SEQ / FILL_RPB;          // 256 chunks per (h,b)
  const int ichunk = blk & (chunks - 1);
  const int hb = blk / chunks;                // h*2 + b
  const int b = hb & 1;
  float4 v = __ldg((const float4*)(g_rowpat + b * SEQ) + threadIdx.x);
  float4* dst =
      (float4*)(attn + ((size_t)hb * SEQ + ichunk * FILL_RPB) * SEQ) + threadIdx.x;
#pragma unroll
  for (int r = 0; r < FILL_RPB; r++)
    __stcs(dst + (size_t)r * (SEQ / 4), v);
}

// ---------------------------------------------------------------------------
static void launch_out_chain(const float* x, const int* mask, const float* Wv,
                             const float* Wo, float* out, float* xbarp,
                             float* vbarp, float* obarp, cudaStream_t st) {
  xbar1_kernel<<<dim3(DIMSZ / 256, NCHUNK, NB), 256, 0, st>>>(x, mask);
  xbar2_kernel<<<dim3(DIMSZ / 256, NB), 256, 0, st>>>();
  gemv_kernel<<<dim3(DIMSZ / 4, NB), 256, 0, st>>>(Wv, xbarp, vbarp);
  gemv_kernel<<<dim3(DIMSZ / 4, NB), 256, 0, st>>>(Wo, vbarp, obarp);
  bcast_out_kernel<<<MROWS / 8, 512, 0, st>>>(out);
}

extern "C" void kernel_launch(void* const* d_in, const int* in_sizes, int n_in,
                              void* d_out, int out_size) {
  const float* x    = (const float*)d_in[0];
  const int*   mask = (const int*)d_in[1];
  // d_in[2]=Wq, d_in[3]=Wk unused: softmax is exactly uniform at scale 2^-50.
  const float* Wv   = (const float*)d_in[4];
  const float* Wo   = (const float*)d_in[5];
  float* out = (float*)d_out;

  float *vbarp, *obarp, *xbarp;
  cudaGetSymbolAddress((void**)&xbarp, g_xbar);
  cudaGetSymbolAddress((void**)&vbarp, g_vbar);
  cudaGetSymbolAddress((void**)&obarp, g_obar);

  const long long OUT_E = (long long)MROWS * DIMSZ;        // 4194304
  const long long ATTN_E = (long long)NH * NB * SEQ * SEQ; // 134217728
  const long long osz = (long long)out_size;
  const bool want_out = (osz != ATTN_E);
  const bool want_attn = (osz >= ATTN_E);
  float* attn_ptr = (osz >= OUT_E + ATTN_E) ? out + OUT_E : out;

  prep_kernel<<<NB, 512>>>(mask);   // capture stream: fill depends on rowpat

  if (want_out && want_attn && g_sh.ok) {
    // Fork after prep: out-chain on side stream, bulk fill on capture stream.
    cudaEventRecord(g_sh.e_fork, 0);
    cudaStreamWaitEvent(g_sh.s, g_sh.e_fork, 0);
    launch_out_chain(x, mask, Wv, Wo, out, xbarp, vbarp, obarp, g_sh.s);
    attn_fill_kernel<<<FILL_GRID, 512>>>(attn_ptr);
    cudaEventRecord(g_sh.e_join, g_sh.s);
    cudaStreamWaitEvent(0, g_sh.e_join, 0);
  } else {
    if (want_out)
      launch_out_chain(x, mask, Wv, Wo, out, xbarp, vbarp, obarp, 0);
    if (want_attn)
      attn_fill_kernel<<<FILL_GRID, 512>>>(attn_ptr);
  }
}